// round 8
// baseline (speedup 1.0000x reference)
#include <cuda_runtime.h>
#include <cuda_bf16.h>
#include <cstdint>

// ---------------------------------------------------------------------------
// WMSA, b=4, H=W=256, c=256, WS=8, HEAD_DIM=32.
// R8: R7 + register double-buffered GEMM mainloops (prefetch kf+1 frags
// before kf's MMA burst), launch_bounds(256,1) to give ptxas the registers.
// ---------------------------------------------------------------------------

#define QKV_SCALE 0.1767766952966369f   // 32^-0.5

// Fragment arrays (bf16). frag = 256 bf16 = 128 u32 = 32 uint4.
__device__ __align__(16) __nv_bfloat16 g_xf_hi[67108864], g_xf_lo[67108864]; // x A-frags [tf][kf=16]
__device__ __align__(16) __nv_bfloat16 g_wqf_hi[196608],  g_wqf_lo[196608];  // w_qkv B-frags [nf=48][kf=16]
__device__ __align__(16) __nv_bfloat16 g_wof_hi[65536],   g_wof_lo[65536];   // w_out B-frags [nf=16][kf=16]
__device__ __align__(16) __nv_bfloat16 g_qf_hi[67108864], g_qf_lo[67108864]; // per blk: A-frags [tf=4][kf=2]
__device__ __align__(16) __nv_bfloat16 g_kf_hi[67108864], g_kf_lo[67108864]; // per blk: B-frags [nf=4][kf=2]
__device__ __align__(16) __nv_bfloat16 g_vf_hi[67108864], g_vf_lo[67108864]; // per blk: VT B-frags [nf=2][kf=4]
__device__ __align__(16) __nv_bfloat16 g_af_hi[67108864], g_af_lo[67108864]; // attn-out A-frags [tf][kf=16]

// ---------------- helpers ----------------
__device__ __forceinline__ void mma_bf16(float* c, const uint32_t* a,
                                         uint32_t b0, uint32_t b1) {
    asm volatile(
        "mma.sync.aligned.m16n8k16.row.col.f32.bf16.bf16.f32 "
        "{%0,%1,%2,%3}, {%4,%5,%6,%7}, {%8,%9}, {%0,%1,%2,%3};"
        : "+f"(c[0]), "+f"(c[1]), "+f"(c[2]), "+f"(c[3])
        : "r"(a[0]), "r"(a[1]), "r"(a[2]), "r"(a[3]), "r"(b0), "r"(b1));
}
__device__ __forceinline__ void split2(float a, float b, uint32_t& h, uint32_t& l) {
    __nv_bfloat16 ha = __float2bfloat16(a), hb = __float2bfloat16(b);
    h = (uint32_t)__bfloat16_as_ushort(ha) | ((uint32_t)__bfloat16_as_ushort(hb) << 16);
    __nv_bfloat16 la = __float2bfloat16(a - __bfloat162float(ha));
    __nv_bfloat16 lb = __float2bfloat16(b - __bfloat162float(hb));
    l = (uint32_t)__bfloat16_as_ushort(la) | ((uint32_t)__bfloat16_as_ushort(lb) << 16);
}

// ---------------------------------------------------------------------------
// cvt_x: gathered (roll+window) tokens -> A-frags. One thread = one lane slot.
// ---------------------------------------------------------------------------
__global__ __launch_bounds__(256) void cvt_x(const float* __restrict__ x) {
    const int gid  = blockIdx.x * 256 + threadIdx.x;
    const int lane = gid & 31;
    const int f    = gid >> 5;          // frag id = tf*16 + kf
    const int kf   = f & 15, tf = f >> 4;
    const int r    = lane >> 2;         // 0..7
    const int c0   = kf * 16 + 2 * (lane & 3);
    // gather rows t0, t0+8
    int t = tf * 16 + r;
    const float* row0; const float* row1;
    {
        int bi = t >> 16, rem = t & 65535, win = rem >> 6, p = rem & 63;
        int hh = (((win >> 5) << 3) + (p >> 3) + 4) & 255;
        int ww = (((win & 31) << 3) + (p & 7) + 4) & 255;
        row0 = x + ((((size_t)bi << 8) + hh) * 256 + ww) * 256;
        t += 8;
        bi = t >> 16; rem = t & 65535; win = rem >> 6; p = rem & 63;
        hh = (((win >> 5) << 3) + (p >> 3) + 4) & 255;
        ww = (((win & 31) << 3) + (p & 7) + 4) & 255;
        row1 = x + ((((size_t)bi << 8) + hh) * 256 + ww) * 256;
    }
    float2 v00 = *(const float2*)(row0 + c0);
    float2 v10 = *(const float2*)(row1 + c0);
    float2 v01 = *(const float2*)(row0 + c0 + 8);
    float2 v11 = *(const float2*)(row1 + c0 + 8);
    uint4 h, l;
    split2(v00.x, v00.y, h.x, l.x);
    split2(v10.x, v10.y, h.y, l.y);
    split2(v01.x, v01.y, h.z, l.z);
    split2(v11.x, v11.y, h.w, l.w);
    ((uint4*)g_xf_hi)[(size_t)f * 32 + lane] = h;
    ((uint4*)g_xf_lo)[(size_t)f * 32 + lane] = l;
}

// cvt weights (row-major [n][256]) -> B-frags. Same slot math, no gather.
__global__ __launch_bounds__(256) void cvt_w(const float* __restrict__ w,
                                             __nv_bfloat16* __restrict__ hi,
                                             __nv_bfloat16* __restrict__ lo) {
    const int gid  = blockIdx.x * 256 + threadIdx.x;
    const int lane = gid & 31;
    const int f    = gid >> 5;          // nf*16 + kf
    const int kf   = f & 15, nf = f >> 4;
    const int r    = lane >> 2;
    const int c0   = kf * 16 + 2 * (lane & 3);
    const float* row0 = w + (size_t)(nf * 16 + r) * 256;
    const float* row1 = row0 + 8 * 256;
    float2 v00 = *(const float2*)(row0 + c0);
    float2 v10 = *(const float2*)(row1 + c0);
    float2 v01 = *(const float2*)(row0 + c0 + 8);
    float2 v11 = *(const float2*)(row1 + c0 + 8);
    uint4 h, l;
    split2(v00.x, v00.y, h.x, l.x);
    split2(v10.x, v10.y, h.y, l.y);
    split2(v01.x, v01.y, h.z, l.z);
    split2(v11.x, v11.y, h.w, l.w);
    ((uint4*)hi)[(size_t)f * 32 + lane] = h;
    ((uint4*)lo)[(size_t)f * 32 + lane] = l;
}

// ---------------------------------------------------------------------------
// Kernel 1: QKV GEMM, smem-free, register double-buffered.
// CTA 128x128, warp 64x32. 16 kf x 3 split terms.
// ---------------------------------------------------------------------------
__global__ __launch_bounds__(256, 1)
void qkv_gemm(const float* __restrict__ bias) {
    const int tid = threadIdx.x;
    const int bn = blockIdx.x;   // 0..5
    const int bm = blockIdx.y;   // 0..2047
    const int lane = tid & 31;
    const int wid  = tid >> 5;
    const int warpM = wid & 1;
    const int warpN = wid >> 1;

    const int tfb = bm * 8 + warpM * 4;
    const int nfb = bn * 8 + warpN * 2;
    const uint4* pAh = (const uint4*)g_xf_hi  + (size_t)tfb * 16 * 32 + lane;
    const uint4* pAl = (const uint4*)g_xf_lo  + (size_t)tfb * 16 * 32 + lane;
    const uint4* pBh = (const uint4*)g_wqf_hi + (size_t)nfb * 16 * 32 + lane;
    const uint4* pBl = (const uint4*)g_wqf_lo + (size_t)nfb * 16 * 32 + lane;

    float acc[4][4][4];
#pragma unroll
    for (int a = 0; a < 4; a++)
#pragma unroll
        for (int b = 0; b < 4; b++)
#pragma unroll
            for (int cR = 0; cR < 4; cR++) acc[a][b][cR] = 0.f;

    uint4 Ah[2][4], Al[2][4], Bh[2][2], Bl[2][2];
#pragma unroll
    for (int mt = 0; mt < 4; mt++) {
        Ah[0][mt] = pAh[(mt * 16) * 32];
        Al[0][mt] = pAl[(mt * 16) * 32];
    }
#pragma unroll
    for (int nb = 0; nb < 2; nb++) {
        Bh[0][nb] = pBh[(nb * 16) * 32];
        Bl[0][nb] = pBl[(nb * 16) * 32];
    }

#pragma unroll
    for (int kf = 0; kf < 16; kf++) {
        const int cb = kf & 1, nb2 = cb ^ 1;
        if (kf < 15) {
#pragma unroll
            for (int mt = 0; mt < 4; mt++) {
                Ah[nb2][mt] = pAh[(mt * 16 + kf + 1) * 32];
                Al[nb2][mt] = pAl[(mt * 16 + kf + 1) * 32];
            }
#pragma unroll
            for (int nb = 0; nb < 2; nb++) {
                Bh[nb2][nb] = pBh[(nb * 16 + kf + 1) * 32];
                Bl[nb2][nb] = pBl[(nb * 16 + kf + 1) * 32];
            }
        }
#pragma unroll
        for (int mt = 0; mt < 4; mt++)
#pragma unroll
            for (int nt = 0; nt < 4; nt++) {
                const uint4& B = Bh[cb][nt >> 1];
                mma_bf16(acc[mt][nt], (const uint32_t*)&Ah[cb][mt],
                         (nt & 1) ? B.y : B.x, (nt & 1) ? B.w : B.z);
            }
#pragma unroll
        for (int mt = 0; mt < 4; mt++)
#pragma unroll
            for (int nt = 0; nt < 4; nt++) {
                const uint4& B = Bh[cb][nt >> 1];
                mma_bf16(acc[mt][nt], (const uint32_t*)&Al[cb][mt],
                         (nt & 1) ? B.y : B.x, (nt & 1) ? B.w : B.z);
            }
#pragma unroll
        for (int mt = 0; mt < 4; mt++)
#pragma unroll
            for (int nt = 0; nt < 4; nt++) {
                const uint4& B = Bl[cb][nt >> 1];
                mma_bf16(acc[mt][nt], (const uint32_t*)&Ah[cb][mt],
                         (nt & 1) ? B.y : B.x, (nt & 1) ? B.w : B.z);
            }
    }

    // Epilogue
    const bool isq = (bn < 2);
    const bool isv = (bn >= 4);
    const int bwq = bm * 2 + warpM;            // b*1024+win for this warp
#pragma unroll
    for (int nt = 0; nt < 4; nt++) {
        const int n = bn * 128 + warpN * 32 + nt * 8 + 2 * (lane & 3);
        const float b0 = __ldg(bias + n), b1 = __ldg(bias + n + 1);
        const int head = (n >> 5) & 7;
        const int d0 = n & 31;
        const size_t blkbase = ((size_t)bwq * 8 + head) * 1024;  // u32 units
#pragma unroll
        for (int mt = 0; mt < 4; mt++) {
#pragma unroll
            for (int rr = 0; rr < 2; rr++) {
                float v0 = acc[mt][nt][rr * 2 + 0] + b0;
                float v1 = acc[mt][nt][rr * 2 + 1] + b1;
                if (isq) { v0 *= QKV_SCALE; v1 *= QKV_SCALE; }
                const int gp = mt * 16 + (lane >> 2) + rr * 8;
                if (!isv) {
                    uint32_t h, l;
                    split2(v0, v1, h, l);
                    const int frag = (gp >> 4) * 2 + (d0 >> 4);
                    const int reg = rr + 2 * (nt & 1);
                    const size_t off = blkbase + frag * 128 + lane * 4 + reg;
                    if (isq) {
                        ((uint32_t*)g_qf_hi)[off] = h;
                        ((uint32_t*)g_qf_lo)[off] = l;
                    } else {
                        ((uint32_t*)g_kf_hi)[off] = h;
                        ((uint32_t*)g_kf_lo)[off] = l;
                    }
                } else {
                    // VT B-frags: pair tokens via shfl_xor(4)
                    const float p0 = __shfl_xor_sync(0xffffffffu, v0, 4);
                    const float p1 = __shfl_xor_sync(0xffffffffu, v1, 4);
                    const bool odd = (lane >> 2) & 1;
                    const float e0 = odd ? p1 : v0;
                    const float e1 = odd ? v1 : p0;
                    const int dmy = d0 + (odd ? 1 : 0);
                    const int gpe = gp & ~1;
                    const int frag = (dmy >> 4) * 4 + (gpe >> 4);
                    const int lane2 = (dmy & 7) * 4 + ((gpe & 7) >> 1);
                    const int reg = (nt & 1) + 2 * rr;
                    uint32_t h, l;
                    split2(e0, e1, h, l);
                    const size_t off = blkbase + frag * 128 + lane2 * 4 + reg;
                    ((uint32_t*)g_vf_hi)[off] = h;
                    ((uint32_t*)g_vf_lo)[off] = l;
                }
            }
        }
    }
}

// ---------------------------------------------------------------------------
// Kernel 2: attention via mma. One block (64 thr, 2 warps) per (b,win,head).
// ---------------------------------------------------------------------------
__global__ __launch_bounds__(64) void attn_kernel(const float* __restrict__ rel_pos) {
    const int blk  = blockIdx.x;
    const int head = blk & 7;
    const int bw   = blk >> 3;
    const int win  = bw & 1023;
    const bool lastH = ((win >> 5) == 31);
    const bool lastW = ((win & 31) == 31);
    const int lane = threadIdx.x & 31;
    const int warp = threadIdx.x >> 5;

    __shared__ float rel_s[240];
    for (int i = threadIdx.x; i < 225; i += 64) rel_s[i] = rel_pos[head * 225 + i];
    __syncthreads();

    // Each block owns 8 frags x 32 uint4 = 256 uint4 per array.
    const uint4* qh = (const uint4*)g_qf_hi + (size_t)blk * 256;
    const uint4* ql = (const uint4*)g_qf_lo + (size_t)blk * 256;
    const uint4* kh = (const uint4*)g_kf_hi + (size_t)blk * 256;
    const uint4* kl = (const uint4*)g_kf_lo + (size_t)blk * 256;
    const uint4* vh = (const uint4*)g_vf_hi + (size_t)blk * 256;
    const uint4* vl = (const uint4*)g_vf_lo + (size_t)blk * 256;

    float S[2][8][4];
#pragma unroll
    for (int a = 0; a < 2; a++)
#pragma unroll
        for (int b = 0; b < 8; b++)
#pragma unroll
            for (int cR = 0; cR < 4; cR++) S[a][b][cR] = 0.f;

    {
        uint4 Q[2][2], K[4][2];
#pragma unroll
        for (int mt = 0; mt < 2; mt++)
#pragma unroll
            for (int kf = 0; kf < 2; kf++)
                Q[mt][kf] = qh[((2 * warp + mt) * 2 + kf) * 32 + lane];
#pragma unroll
        for (int nf = 0; nf < 4; nf++)
#pragma unroll
            for (int kf = 0; kf < 2; kf++)
                K[nf][kf] = kh[(nf * 2 + kf) * 32 + lane];
#pragma unroll
        for (int kf = 0; kf < 2; kf++)
#pragma unroll
            for (int mt = 0; mt < 2; mt++)
#pragma unroll
                for (int nt = 0; nt < 8; nt++) {
                    const uint4& B = K[nt >> 1][kf];
                    mma_bf16(S[mt][nt], (const uint32_t*)&Q[mt][kf],
                             (nt & 1) ? B.y : B.x, (nt & 1) ? B.w : B.z);
                }
        uint4 Q2[2][2];
#pragma unroll
        for (int mt = 0; mt < 2; mt++)
#pragma unroll
            for (int kf = 0; kf < 2; kf++)
                Q2[mt][kf] = ql[((2 * warp + mt) * 2 + kf) * 32 + lane];
#pragma unroll
        for (int kf = 0; kf < 2; kf++)
#pragma unroll
            for (int mt = 0; mt < 2; mt++)
#pragma unroll
                for (int nt = 0; nt < 8; nt++) {
                    const uint4& B = K[nt >> 1][kf];
                    mma_bf16(S[mt][nt], (const uint32_t*)&Q2[mt][kf],
                             (nt & 1) ? B.y : B.x, (nt & 1) ? B.w : B.z);
                }
#pragma unroll
        for (int nf = 0; nf < 4; nf++)
#pragma unroll
            for (int kf = 0; kf < 2; kf++)
                K[nf][kf] = kl[(nf * 2 + kf) * 32 + lane];
#pragma unroll
        for (int kf = 0; kf < 2; kf++)
#pragma unroll
            for (int mt = 0; mt < 2; mt++)
#pragma unroll
                for (int nt = 0; nt < 8; nt++) {
                    const uint4& B = K[nt >> 1][kf];
                    mma_bf16(S[mt][nt], (const uint32_t*)&Q[mt][kf],
                             (nt & 1) ? B.y : B.x, (nt & 1) ? B.w : B.z);
                }
    }

    // bias + mask
#pragma unroll
    for (int mt = 0; mt < 2; mt++) {
        const int p_lo = warp * 32 + mt * 16 + (lane >> 2);
        const int p_hi = p_lo + 8;
        const int pi0 = p_lo >> 3, pj0 = p_lo & 7;
        const int pi1 = p_hi >> 3, pj1 = p_hi & 7;
#pragma unroll
        for (int nt = 0; nt < 8; nt++) {
            const int j0 = nt * 8 + 2 * (lane & 3);
#pragma unroll
            for (int jj = 0; jj < 2; jj++) {
                const int j = j0 + jj;
                const int qi = j >> 3, qj = j & 7;
                float r0 = rel_s[(pi0 - qi + 7) * 15 + (pj0 - qj + 7)];
                float r1 = rel_s[(pi1 - qi + 7) * 15 + (pj1 - qj + 7)];
                float s0 = S[mt][nt][jj] + r0;
                float s1 = S[mt][nt][2 + jj] + r1;
                if ((lastH && ((pi0 < 4) != (qi < 4))) || (lastW && ((pj0 < 4) != (qj < 4))))
                    s0 = -1e30f;
                if ((lastH && ((pi1 < 4) != (qi < 4))) || (lastW && ((pj1 < 4) != (qj < 4))))
                    s1 = -1e30f;
                S[mt][nt][jj] = s0;
                S[mt][nt][2 + jj] = s1;
            }
        }
    }

    // softmax per row
    float O[2][4][4];
#pragma unroll
    for (int a = 0; a < 2; a++)
#pragma unroll
        for (int b = 0; b < 4; b++)
#pragma unroll
            for (int cR = 0; cR < 4; cR++) O[a][b][cR] = 0.f;

    uint32_t Ph[2][4][4], Pl[2][4][4];
#pragma unroll
    for (int mt = 0; mt < 2; mt++) {
        float m0 = -3.0e38f, m1 = -3.0e38f;
#pragma unroll
        for (int nt = 0; nt < 8; nt++) {
            m0 = fmaxf(m0, fmaxf(S[mt][nt][0], S[mt][nt][1]));
            m1 = fmaxf(m1, fmaxf(S[mt][nt][2], S[mt][nt][3]));
        }
        m0 = fmaxf(m0, __shfl_xor_sync(0xffffffffu, m0, 1));
        m0 = fmaxf(m0, __shfl_xor_sync(0xffffffffu, m0, 2));
        m1 = fmaxf(m1, __shfl_xor_sync(0xffffffffu, m1, 1));
        m1 = fmaxf(m1, __shfl_xor_sync(0xffffffffu, m1, 2));
        float s0 = 0.f, s1 = 0.f;
#pragma unroll
        for (int nt = 0; nt < 8; nt++) {
            S[mt][nt][0] = __expf(S[mt][nt][0] - m0);
            S[mt][nt][1] = __expf(S[mt][nt][1] - m0);
            S[mt][nt][2] = __expf(S[mt][nt][2] - m1);
            S[mt][nt][3] = __expf(S[mt][nt][3] - m1);
            s0 += S[mt][nt][0] + S[mt][nt][1];
            s1 += S[mt][nt][2] + S[mt][nt][3];
        }
        s0 += __shfl_xor_sync(0xffffffffu, s0, 1);
        s0 += __shfl_xor_sync(0xffffffffu, s0, 2);
        s1 += __shfl_xor_sync(0xffffffffu, s1, 1);
        s1 += __shfl_xor_sync(0xffffffffu, s1, 2);
        const float i0 = 1.f / s0, i1 = 1.f / s1;
        // pack P as A-frags: kf covers nt pair (2kf, 2kf+1)
#pragma unroll
        for (int kf = 0; kf < 4; kf++) {
            split2(S[mt][2 * kf][0] * i0, S[mt][2 * kf][1] * i0, Ph[mt][kf][0], Pl[mt][kf][0]);
            split2(S[mt][2 * kf][2] * i1, S[mt][2 * kf][3] * i1, Ph[mt][kf][1], Pl[mt][kf][1]);
            split2(S[mt][2 * kf + 1][0] * i0, S[mt][2 * kf + 1][1] * i0, Ph[mt][kf][2], Pl[mt][kf][2]);
            split2(S[mt][2 * kf + 1][2] * i1, S[mt][2 * kf + 1][3] * i1, Ph[mt][kf][3], Pl[mt][kf][3]);
        }
    }

    {
        uint4 V[2][4];
#pragma unroll
        for (int nf = 0; nf < 2; nf++)
#pragma unroll
            for (int kf = 0; kf < 4; kf++)
                V[nf][kf] = vh[(nf * 4 + kf) * 32 + lane];
#pragma unroll
        for (int kf = 0; kf < 4; kf++)
#pragma unroll
            for (int mt = 0; mt < 2; mt++)
#pragma unroll
                for (int nd = 0; nd < 4; nd++) {
                    const uint4& B = V[nd >> 1][kf];
                    mma_bf16(O[mt][nd], Ph[mt][kf],
                             (nd & 1) ? B.y : B.x, (nd & 1) ? B.w : B.z);
                }
#pragma unroll
        for (int kf = 0; kf < 4; kf++)
#pragma unroll
            for (int mt = 0; mt < 2; mt++)
#pragma unroll
                for (int nd = 0; nd < 4; nd++) {
                    const uint4& B = V[nd >> 1][kf];
                    mma_bf16(O[mt][nd], Pl[mt][kf],
                             (nd & 1) ? B.y : B.x, (nd & 1) ? B.w : B.z);
                }
#pragma unroll
        for (int nf = 0; nf < 2; nf++)
#pragma unroll
            for (int kf = 0; kf < 4; kf++)
                V[nf][kf] = vl[(nf * 4 + kf) * 32 + lane];
#pragma unroll
        for (int kf = 0; kf < 4; kf++)
#pragma unroll
            for (int mt = 0; mt < 2; mt++)
#pragma unroll
                for (int nd = 0; nd < 4; nd++) {
                    const uint4& B = V[nd >> 1][kf];
                    mma_bf16(O[mt][nd], Ph[mt][kf],
                             (nd & 1) ? B.y : B.x, (nd & 1) ? B.w : B.z);
                }
    }

    // Epilogue: O -> attn-out A-frags (t = bw*64 + p, channel = head*32 + d)
#pragma unroll
    for (int mt = 0; mt < 2; mt++) {
        const int tf = bw * 4 + warp * 2 + mt;
#pragma unroll
        for (int nd = 0; nd < 4; nd++) {
            const int ch = head * 32 + nd * 8 + 2 * (lane & 3);
            const int chf = ch >> 4;
            uint32_t h0, l0, h1, l1;
            split2(O[mt][nd][0], O[mt][nd][1], h0, l0);
            split2(O[mt][nd][2], O[mt][nd][3], h1, l1);
            const size_t off = ((size_t)tf * 16 + chf) * 128 + lane * 4 + 2 * (nd & 1);
            ((uint32_t*)g_af_hi)[off]     = h0;
            ((uint32_t*)g_af_hi)[off + 1] = h1;
            ((uint32_t*)g_af_lo)[off]     = l0;
            ((uint32_t*)g_af_lo)[off + 1] = l1;
        }
    }
}

// ---------------------------------------------------------------------------
// Kernel 3: output projection, register double-buffered; epilogue = scrambled
// reshape + roll.
// ---------------------------------------------------------------------------
__global__ __launch_bounds__(256, 1)
void out_gemm(const float* __restrict__ bias, float* __restrict__ out) {
    const int tid = threadIdx.x;
    const int bn = blockIdx.x;   // 0..1
    const int bm = blockIdx.y;   // 0..2047
    const int lane = tid & 31;
    const int wid  = tid >> 5;
    const int warpM = wid & 1;
    const int warpN = wid >> 1;

    const int tfb = bm * 8 + warpM * 4;
    const int nfb = bn * 8 + warpN * 2;
    const uint4* pAh = (const uint4*)g_af_hi  + (size_t)tfb * 16 * 32 + lane;
    const uint4* pAl = (const uint4*)g_af_lo  + (size_t)tfb * 16 * 32 + lane;
    const uint4* pBh = (const uint4*)g_wof_hi + (size_t)nfb * 16 * 32 + lane;
    const uint4* pBl = (const uint4*)g_wof_lo + (size_t)nfb * 16 * 32 + lane;

    float acc[4][4][4];
#pragma unroll
    for (int a = 0; a < 4; a++)
#pragma unroll
        for (int b = 0; b < 4; b++)
#pragma unroll
            for (int cR = 0; cR < 4; cR++) acc[a][b][cR] = 0.f;

    uint4 Ah[2][4], Al[2][4], Bh[2][2], Bl[2][2];
#pragma unroll
    for (int mt = 0; mt < 4; mt++) {
        Ah[0][mt] = pAh[(mt * 16) * 32];
        Al[0][mt] = pAl[(mt * 16) * 32];
    }
#pragma unroll
    for (int nb = 0; nb < 2; nb++) {
        Bh[0][nb] = pBh[(nb * 16) * 32];
        Bl[0][nb] = pBl[(nb * 16) * 32];
    }

#pragma unroll
    for (int kf = 0; kf < 16; kf++) {
        const int cb = kf & 1, nb2 = cb ^ 1;
        if (kf < 15) {
#pragma unroll
            for (int mt = 0; mt < 4; mt++) {
                Ah[nb2][mt] = pAh[(mt * 16 + kf + 1) * 32];
                Al[nb2][mt] = pAl[(mt * 16 + kf + 1) * 32];
            }
#pragma unroll
            for (int nb = 0; nb < 2; nb++) {
                Bh[nb2][nb] = pBh[(nb * 16 + kf + 1) * 32];
                Bl[nb2][nb] = pBl[(nb * 16 + kf + 1) * 32];
            }
        }
#pragma unroll
        for (int mt = 0; mt < 4; mt++)
#pragma unroll
            for (int nt = 0; nt < 4; nt++) {
                const uint4& B = Bh[cb][nt >> 1];
                mma_bf16(acc[mt][nt], (const uint32_t*)&Ah[cb][mt],
                         (nt & 1) ? B.y : B.x, (nt & 1) ? B.w : B.z);
            }
#pragma unroll
        for (int mt = 0; mt < 4; mt++)
#pragma unroll
            for (int nt = 0; nt < 4; nt++) {
                const uint4& B = Bh[cb][nt >> 1];
                mma_bf16(acc[mt][nt], (const uint32_t*)&Al[cb][mt],
                         (nt & 1) ? B.y : B.x, (nt & 1) ? B.w : B.z);
            }
#pragma unroll
        for (int mt = 0; mt < 4; mt++)
#pragma unroll
            for (int nt = 0; nt < 4; nt++) {
                const uint4& B = Bl[cb][nt >> 1];
                mma_bf16(acc[mt][nt], (const uint32_t*)&Ah[cb][mt],
                         (nt & 1) ? B.y : B.x, (nt & 1) ? B.w : B.z);
            }
    }

#pragma unroll
    for (int mt = 0; mt < 4; mt++) {
#pragma unroll
        for (int rr = 0; rr < 2; rr++) {
            const int gt   = bm * 128 + warpM * 64 + mt * 16 + (lane >> 2) + rr * 8;
            const int gbi  = gt >> 16;
            const int grem = gt & 65535;
            const int gwin = grem >> 6;
            const int gp   = grem & 63;
            const int L  = gwin * 4 + gbi;    // reference's scrambled flatten
            const int a  = L >> 10;
            const int r  = (L >> 5) & 31;
            const int s  = L & 31;
            const int hh  = ((r << 3) + (gp >> 3) + 4) & 255;
            const int wwp = ((s << 3) + (gp & 7) + 4) & 255;
            float* orow = out + ((((size_t)a << 8) + hh) * 256 + wwp) * 256;
#pragma unroll
            for (int nt = 0; nt < 4; nt++) {
                const int n = bn * 128 + warpN * 32 + nt * 8 + 2 * (lane & 3);
                *(float2*)&orow[n] =
                    make_float2(acc[mt][nt][rr * 2 + 0] + __ldg(bias + n),
                                acc[mt][nt][rr * 2 + 1] + __ldg(bias + n + 1));
            }
        }
    }
}

// ---------------------------------------------------------------------------
extern "C" void kernel_launch(void* const* d_in, const int* in_sizes, int n_in,
                              void* d_out, int out_size) {
    const float* x      = (const float*)d_in[0];
    const float* w_qkv  = (const float*)d_in[1];
    const float* b_qkv  = (const float*)d_in[2];
    const float* rel    = (const float*)d_in[3];
    const float* w_out  = (const float*)d_in[4];
    const float* b_out  = (const float*)d_in[5];
    float* out = (float*)d_out;

    __nv_bfloat16 *wq_hi, *wq_lo, *wo_hi, *wo_lo;
    cudaGetSymbolAddress((void**)&wq_hi, g_wqf_hi);
    cudaGetSymbolAddress((void**)&wq_lo, g_wqf_lo);
    cudaGetSymbolAddress((void**)&wo_hi, g_wof_hi);
    cudaGetSymbolAddress((void**)&wo_lo, g_wof_lo);

    cvt_x<<<32768, 256>>>(x);
    cvt_w<<<96, 256>>>(w_qkv, wq_hi, wq_lo);
    cvt_w<<<32, 256>>>(w_out, wo_hi, wo_lo);
    qkv_gemm<<<dim3(6, 2048), 256>>>(b_qkv);
    attn_kernel<<<32768, 64>>>(rel);
    out_gemm<<<dim3(2, 2048), 256>>>(b_out, out);
}

// round 9
// speedup vs baseline: 1.1561x; 1.1561x over previous
#include <cuda_runtime.h>
#include <cuda_bf16.h>
#include <cstdint>

// ---------------------------------------------------------------------------
// WMSA, b=4, H=W=256, c=256, WS=8, HEAD_DIM=32.
// R9: GEMM CTAs shrunk to 128 threads (4 warps, 2x2), warp tile 64x64.
// 2 CTAs/SM at <=255 regs keeps 8 warps/SM while doubling the MMA burst
// per load round (96 HMMA / 16 LDG). Attention/cvt unchanged from R7.
// ---------------------------------------------------------------------------

#define QKV_SCALE 0.1767766952966369f   // 32^-0.5

// Fragment arrays (bf16). frag = 256 bf16 = 128 u32 = 32 uint4.
__device__ __align__(16) __nv_bfloat16 g_xf_hi[67108864], g_xf_lo[67108864]; // x A-frags [tf][kf=16]
__device__ __align__(16) __nv_bfloat16 g_wqf_hi[196608],  g_wqf_lo[196608];  // w_qkv B-frags [nf=48][kf=16]
__device__ __align__(16) __nv_bfloat16 g_wof_hi[65536],   g_wof_lo[65536];   // w_out B-frags [nf=16][kf=16]
__device__ __align__(16) __nv_bfloat16 g_qf_hi[67108864], g_qf_lo[67108864]; // per blk: A-frags [tf=4][kf=2]
__device__ __align__(16) __nv_bfloat16 g_kf_hi[67108864], g_kf_lo[67108864]; // per blk: B-frags [nf=4][kf=2]
__device__ __align__(16) __nv_bfloat16 g_vf_hi[67108864], g_vf_lo[67108864]; // per blk: VT B-frags [nf=2][kf=4]
__device__ __align__(16) __nv_bfloat16 g_af_hi[67108864], g_af_lo[67108864]; // attn-out A-frags [tf][kf=16]

// ---------------- helpers ----------------
__device__ __forceinline__ void mma_bf16(float* c, const uint32_t* a,
                                         uint32_t b0, uint32_t b1) {
    asm volatile(
        "mma.sync.aligned.m16n8k16.row.col.f32.bf16.bf16.f32 "
        "{%0,%1,%2,%3}, {%4,%5,%6,%7}, {%8,%9}, {%0,%1,%2,%3};"
        : "+f"(c[0]), "+f"(c[1]), "+f"(c[2]), "+f"(c[3])
        : "r"(a[0]), "r"(a[1]), "r"(a[2]), "r"(a[3]), "r"(b0), "r"(b1));
}
__device__ __forceinline__ void split2(float a, float b, uint32_t& h, uint32_t& l) {
    __nv_bfloat16 ha = __float2bfloat16(a), hb = __float2bfloat16(b);
    h = (uint32_t)__bfloat16_as_ushort(ha) | ((uint32_t)__bfloat16_as_ushort(hb) << 16);
    __nv_bfloat16 la = __float2bfloat16(a - __bfloat162float(ha));
    __nv_bfloat16 lb = __float2bfloat16(b - __bfloat162float(hb));
    l = (uint32_t)__bfloat16_as_ushort(la) | ((uint32_t)__bfloat16_as_ushort(lb) << 16);
}

// ---------------------------------------------------------------------------
// cvt_x: gathered (roll+window) tokens -> A-frags. One thread = one lane slot.
// ---------------------------------------------------------------------------
__global__ __launch_bounds__(256) void cvt_x(const float* __restrict__ x) {
    const int gid  = blockIdx.x * 256 + threadIdx.x;
    const int lane = gid & 31;
    const int f    = gid >> 5;          // frag id = tf*16 + kf
    const int kf   = f & 15, tf = f >> 4;
    const int r    = lane >> 2;         // 0..7
    const int c0   = kf * 16 + 2 * (lane & 3);
    // gather rows t0, t0+8
    int t = tf * 16 + r;
    const float* row0; const float* row1;
    {
        int bi = t >> 16, rem = t & 65535, win = rem >> 6, p = rem & 63;
        int hh = (((win >> 5) << 3) + (p >> 3) + 4) & 255;
        int ww = (((win & 31) << 3) + (p & 7) + 4) & 255;
        row0 = x + ((((size_t)bi << 8) + hh) * 256 + ww) * 256;
        t += 8;
        bi = t >> 16; rem = t & 65535; win = rem >> 6; p = rem & 63;
        hh = (((win >> 5) << 3) + (p >> 3) + 4) & 255;
        ww = (((win & 31) << 3) + (p & 7) + 4) & 255;
        row1 = x + ((((size_t)bi << 8) + hh) * 256 + ww) * 256;
    }
    float2 v00 = *(const float2*)(row0 + c0);
    float2 v10 = *(const float2*)(row1 + c0);
    float2 v01 = *(const float2*)(row0 + c0 + 8);
    float2 v11 = *(const float2*)(row1 + c0 + 8);
    uint4 h, l;
    split2(v00.x, v00.y, h.x, l.x);
    split2(v10.x, v10.y, h.y, l.y);
    split2(v01.x, v01.y, h.z, l.z);
    split2(v11.x, v11.y, h.w, l.w);
    ((uint4*)g_xf_hi)[(size_t)f * 32 + lane] = h;
    ((uint4*)g_xf_lo)[(size_t)f * 32 + lane] = l;
}

// cvt weights (row-major [n][256]) -> B-frags. Same slot math, no gather.
__global__ __launch_bounds__(256) void cvt_w(const float* __restrict__ w,
                                             __nv_bfloat16* __restrict__ hi,
                                             __nv_bfloat16* __restrict__ lo) {
    const int gid  = blockIdx.x * 256 + threadIdx.x;
    const int lane = gid & 31;
    const int f    = gid >> 5;          // nf*16 + kf
    const int kf   = f & 15, nf = f >> 4;
    const int r    = lane >> 2;
    const int c0   = kf * 16 + 2 * (lane & 3);
    const float* row0 = w + (size_t)(nf * 16 + r) * 256;
    const float* row1 = row0 + 8 * 256;
    float2 v00 = *(const float2*)(row0 + c0);
    float2 v10 = *(const float2*)(row1 + c0);
    float2 v01 = *(const float2*)(row0 + c0 + 8);
    float2 v11 = *(const float2*)(row1 + c0 + 8);
    uint4 h, l;
    split2(v00.x, v00.y, h.x, l.x);
    split2(v10.x, v10.y, h.y, l.y);
    split2(v01.x, v01.y, h.z, l.z);
    split2(v11.x, v11.y, h.w, l.w);
    ((uint4*)hi)[(size_t)f * 32 + lane] = h;
    ((uint4*)lo)[(size_t)f * 32 + lane] = l;
}

// ---------------------------------------------------------------------------
// Kernel 1: QKV GEMM. 128-thread CTA, 4 warps (2x2), warp tile 64x64.
// 16 kf x 3 split terms, 96 HMMA / 16 LDG per iteration.
// ---------------------------------------------------------------------------
__global__ __launch_bounds__(128)
void qkv_gemm(const float* __restrict__ bias) {
    const int tid = threadIdx.x;
    const int bn = blockIdx.x;   // 0..5
    const int bm = blockIdx.y;   // 0..2047
    const int lane = tid & 31;
    const int wid  = tid >> 5;
    const int warpM = wid & 1;   // 2 x 64 rows
    const int warpN = wid >> 1;  // 2 x 64 cols

    const int tfb = bm * 8 + warpM * 4;
    const int nfb = bn * 8 + warpN * 4;
    const uint4* pAh = (const uint4*)g_xf_hi  + (size_t)tfb * 16 * 32 + lane;
    const uint4* pAl = (const uint4*)g_xf_lo  + (size_t)tfb * 16 * 32 + lane;
    const uint4* pBh = (const uint4*)g_wqf_hi + (size_t)nfb * 16 * 32 + lane;
    const uint4* pBl = (const uint4*)g_wqf_lo + (size_t)nfb * 16 * 32 + lane;

    float acc[4][8][4];
#pragma unroll
    for (int a = 0; a < 4; a++)
#pragma unroll
        for (int b = 0; b < 8; b++)
#pragma unroll
            for (int cR = 0; cR < 4; cR++) acc[a][b][cR] = 0.f;

#pragma unroll
    for (int kf = 0; kf < 16; kf++) {
        uint4 Ah[4], Al[4], Bh[4], Bl[4];
#pragma unroll
        for (int mt = 0; mt < 4; mt++) {
            Ah[mt] = pAh[(mt * 16 + kf) * 32];
            Al[mt] = pAl[(mt * 16 + kf) * 32];
        }
#pragma unroll
        for (int nb = 0; nb < 4; nb++) {
            Bh[nb] = pBh[(nb * 16 + kf) * 32];
            Bl[nb] = pBl[(nb * 16 + kf) * 32];
        }
#pragma unroll
        for (int mt = 0; mt < 4; mt++)
#pragma unroll
            for (int nt = 0; nt < 8; nt++) {
                const uint4& B = Bh[nt >> 1];
                mma_bf16(acc[mt][nt], (const uint32_t*)&Ah[mt],
                         (nt & 1) ? B.y : B.x, (nt & 1) ? B.w : B.z);
            }
#pragma unroll
        for (int mt = 0; mt < 4; mt++)
#pragma unroll
            for (int nt = 0; nt < 8; nt++) {
                const uint4& B = Bh[nt >> 1];
                mma_bf16(acc[mt][nt], (const uint32_t*)&Al[mt],
                         (nt & 1) ? B.y : B.x, (nt & 1) ? B.w : B.z);
            }
#pragma unroll
        for (int mt = 0; mt < 4; mt++)
#pragma unroll
            for (int nt = 0; nt < 8; nt++) {
                const uint4& B = Bl[nt >> 1];
                mma_bf16(acc[mt][nt], (const uint32_t*)&Ah[mt],
                         (nt & 1) ? B.y : B.x, (nt & 1) ? B.w : B.z);
            }
    }

    // Epilogue
    const bool isq = (bn < 2);
    const bool isv = (bn >= 4);
    const int bwq = bm * 2 + warpM;            // b*1024+win for this warp
#pragma unroll
    for (int nt = 0; nt < 8; nt++) {
        const int n = bn * 128 + warpN * 64 + nt * 8 + 2 * (lane & 3);
        const float b0 = __ldg(bias + n), b1 = __ldg(bias + n + 1);
        const int head = (n >> 5) & 7;
        const int d0 = n & 31;
        const size_t blkbase = ((size_t)bwq * 8 + head) * 1024;  // u32 units
#pragma unroll
        for (int mt = 0; mt < 4; mt++) {
#pragma unroll
            for (int rr = 0; rr < 2; rr++) {
                float v0 = acc[mt][nt][rr * 2 + 0] + b0;
                float v1 = acc[mt][nt][rr * 2 + 1] + b1;
                if (isq) { v0 *= QKV_SCALE; v1 *= QKV_SCALE; }
                const int gp = mt * 16 + (lane >> 2) + rr * 8;
                if (!isv) {
                    uint32_t h, l;
                    split2(v0, v1, h, l);
                    const int frag = (gp >> 4) * 2 + (d0 >> 4);
                    const int reg = rr + 2 * (nt & 1);
                    const size_t off = blkbase + frag * 128 + lane * 4 + reg;
                    if (isq) {
                        ((uint32_t*)g_qf_hi)[off] = h;
                        ((uint32_t*)g_qf_lo)[off] = l;
                    } else {
                        ((uint32_t*)g_kf_hi)[off] = h;
                        ((uint32_t*)g_kf_lo)[off] = l;
                    }
                } else {
                    // VT B-frags: pair tokens via shfl_xor(4)
                    const float p0 = __shfl_xor_sync(0xffffffffu, v0, 4);
                    const float p1 = __shfl_xor_sync(0xffffffffu, v1, 4);
                    const bool odd = (lane >> 2) & 1;
                    const float e0 = odd ? p1 : v0;
                    const float e1 = odd ? v1 : p0;
                    const int dmy = d0 + (odd ? 1 : 0);
                    const int gpe = gp & ~1;
                    const int frag = (dmy >> 4) * 4 + (gpe >> 4);
                    const int lane2 = (dmy & 7) * 4 + ((gpe & 7) >> 1);
                    const int reg = (nt & 1) + 2 * rr;
                    uint32_t h, l;
                    split2(e0, e1, h, l);
                    const size_t off = blkbase + frag * 128 + lane2 * 4 + reg;
                    ((uint32_t*)g_vf_hi)[off] = h;
                    ((uint32_t*)g_vf_lo)[off] = l;
                }
            }
        }
    }
}

// ---------------------------------------------------------------------------
// Kernel 2: attention via mma. One block (64 thr, 2 warps) per (b,win,head).
// ---------------------------------------------------------------------------
__global__ __launch_bounds__(64) void attn_kernel(const float* __restrict__ rel_pos) {
    const int blk  = blockIdx.x;
    const int head = blk & 7;
    const int bw   = blk >> 3;
    const int win  = bw & 1023;
    const bool lastH = ((win >> 5) == 31);
    const bool lastW = ((win & 31) == 31);
    const int lane = threadIdx.x & 31;
    const int warp = threadIdx.x >> 5;

    __shared__ float rel_s[240];
    for (int i = threadIdx.x; i < 225; i += 64) rel_s[i] = rel_pos[head * 225 + i];
    __syncthreads();

    // Each block owns 8 frags x 32 uint4 = 256 uint4 per array.
    const uint4* qh = (const uint4*)g_qf_hi + (size_t)blk * 256;
    const uint4* ql = (const uint4*)g_qf_lo + (size_t)blk * 256;
    const uint4* kh = (const uint4*)g_kf_hi + (size_t)blk * 256;
    const uint4* kl = (const uint4*)g_kf_lo + (size_t)blk * 256;
    const uint4* vh = (const uint4*)g_vf_hi + (size_t)blk * 256;
    const uint4* vl = (const uint4*)g_vf_lo + (size_t)blk * 256;

    float S[2][8][4];
#pragma unroll
    for (int a = 0; a < 2; a++)
#pragma unroll
        for (int b = 0; b < 8; b++)
#pragma unroll
            for (int cR = 0; cR < 4; cR++) S[a][b][cR] = 0.f;

    {
        uint4 Q[2][2], K[4][2];
#pragma unroll
        for (int mt = 0; mt < 2; mt++)
#pragma unroll
            for (int kf = 0; kf < 2; kf++)
                Q[mt][kf] = qh[((2 * warp + mt) * 2 + kf) * 32 + lane];
#pragma unroll
        for (int nf = 0; nf < 4; nf++)
#pragma unroll
            for (int kf = 0; kf < 2; kf++)
                K[nf][kf] = kh[(nf * 2 + kf) * 32 + lane];
#pragma unroll
        for (int kf = 0; kf < 2; kf++)
#pragma unroll
            for (int mt = 0; mt < 2; mt++)
#pragma unroll
                for (int nt = 0; nt < 8; nt++) {
                    const uint4& B = K[nt >> 1][kf];
                    mma_bf16(S[mt][nt], (const uint32_t*)&Q[mt][kf],
                             (nt & 1) ? B.y : B.x, (nt & 1) ? B.w : B.z);
                }
        uint4 Q2[2][2];
#pragma unroll
        for (int mt = 0; mt < 2; mt++)
#pragma unroll
            for (int kf = 0; kf < 2; kf++)
                Q2[mt][kf] = ql[((2 * warp + mt) * 2 + kf) * 32 + lane];
#pragma unroll
        for (int kf = 0; kf < 2; kf++)
#pragma unroll
            for (int mt = 0; mt < 2; mt++)
#pragma unroll
                for (int nt = 0; nt < 8; nt++) {
                    const uint4& B = K[nt >> 1][kf];
                    mma_bf16(S[mt][nt], (const uint32_t*)&Q2[mt][kf],
                             (nt & 1) ? B.y : B.x, (nt & 1) ? B.w : B.z);
                }
#pragma unroll
        for (int nf = 0; nf < 4; nf++)
#pragma unroll
            for (int kf = 0; kf < 2; kf++)
                K[nf][kf] = kl[(nf * 2 + kf) * 32 + lane];
#pragma unroll
        for (int kf = 0; kf < 2; kf++)
#pragma unroll
            for (int mt = 0; mt < 2; mt++)
#pragma unroll
                for (int nt = 0; nt < 8; nt++) {
                    const uint4& B = K[nt >> 1][kf];
                    mma_bf16(S[mt][nt], (const uint32_t*)&Q[mt][kf],
                             (nt & 1) ? B.y : B.x, (nt & 1) ? B.w : B.z);
                }
    }

    // bias + mask
#pragma unroll
    for (int mt = 0; mt < 2; mt++) {
        const int p_lo = warp * 32 + mt * 16 + (lane >> 2);
        const int p_hi = p_lo + 8;
        const int pi0 = p_lo >> 3, pj0 = p_lo & 7;
        const int pi1 = p_hi >> 3, pj1 = p_hi & 7;
#pragma unroll
        for (int nt = 0; nt < 8; nt++) {
            const int j0 = nt * 8 + 2 * (lane & 3);
#pragma unroll
            for (int jj = 0; jj < 2; jj++) {
                const int j = j0 + jj;
                const int qi = j >> 3, qj = j & 7;
                float r0 = rel_s[(pi0 - qi + 7) * 15 + (pj0 - qj + 7)];
                float r1 = rel_s[(pi1 - qi + 7) * 15 + (pj1 - qj + 7)];
                float s0 = S[mt][nt][jj] + r0;
                float s1 = S[mt][nt][2 + jj] + r1;
                if ((lastH && ((pi0 < 4) != (qi < 4))) || (lastW && ((pj0 < 4) != (qj < 4))))
                    s0 = -1e30f;
                if ((lastH && ((pi1 < 4) != (qi < 4))) || (lastW && ((pj1 < 4) != (qj < 4))))
                    s1 = -1e30f;
                S[mt][nt][jj] = s0;
                S[mt][nt][2 + jj] = s1;
            }
        }
    }

    // softmax per row
    float O[2][4][4];
#pragma unroll
    for (int a = 0; a < 2; a++)
#pragma unroll
        for (int b = 0; b < 4; b++)
#pragma unroll
            for (int cR = 0; cR < 4; cR++) O[a][b][cR] = 0.f;

    uint32_t Ph[2][4][4], Pl[2][4][4];
#pragma unroll
    for (int mt = 0; mt < 2; mt++) {
        float m0 = -3.0e38f, m1 = -3.0e38f;
#pragma unroll
        for (int nt = 0; nt < 8; nt++) {
            m0 = fmaxf(m0, fmaxf(S[mt][nt][0], S[mt][nt][1]));
            m1 = fmaxf(m1, fmaxf(S[mt][nt][2], S[mt][nt][3]));
        }
        m0 = fmaxf(m0, __shfl_xor_sync(0xffffffffu, m0, 1));
        m0 = fmaxf(m0, __shfl_xor_sync(0xffffffffu, m0, 2));
        m1 = fmaxf(m1, __shfl_xor_sync(0xffffffffu, m1, 1));
        m1 = fmaxf(m1, __shfl_xor_sync(0xffffffffu, m1, 2));
        float s0 = 0.f, s1 = 0.f;
#pragma unroll
        for (int nt = 0; nt < 8; nt++) {
            S[mt][nt][0] = __expf(S[mt][nt][0] - m0);
            S[mt][nt][1] = __expf(S[mt][nt][1] - m0);
            S[mt][nt][2] = __expf(S[mt][nt][2] - m1);
            S[mt][nt][3] = __expf(S[mt][nt][3] - m1);
            s0 += S[mt][nt][0] + S[mt][nt][1];
            s1 += S[mt][nt][2] + S[mt][nt][3];
        }
        s0 += __shfl_xor_sync(0xffffffffu, s0, 1);
        s0 += __shfl_xor_sync(0xffffffffu, s0, 2);
        s1 += __shfl_xor_sync(0xffffffffu, s1, 1);
        s1 += __shfl_xor_sync(0xffffffffu, s1, 2);
        const float i0 = 1.f / s0, i1 = 1.f / s1;
        // pack P as A-frags: kf covers nt pair (2kf, 2kf+1)
#pragma unroll
        for (int kf = 0; kf < 4; kf++) {
            split2(S[mt][2 * kf][0] * i0, S[mt][2 * kf][1] * i0, Ph[mt][kf][0], Pl[mt][kf][0]);
            split2(S[mt][2 * kf][2] * i1, S[mt][2 * kf][3] * i1, Ph[mt][kf][1], Pl[mt][kf][1]);
            split2(S[mt][2 * kf + 1][0] * i0, S[mt][2 * kf + 1][1] * i0, Ph[mt][kf][2], Pl[mt][kf][2]);
            split2(S[mt][2 * kf + 1][2] * i1, S[mt][2 * kf + 1][3] * i1, Ph[mt][kf][3], Pl[mt][kf][3]);
        }
    }

    {
        uint4 V[2][4];
#pragma unroll
        for (int nf = 0; nf < 2; nf++)
#pragma unroll
            for (int kf = 0; kf < 4; kf++)
                V[nf][kf] = vh[(nf * 4 + kf) * 32 + lane];
#pragma unroll
        for (int kf = 0; kf < 4; kf++)
#pragma unroll
            for (int mt = 0; mt < 2; mt++)
#pragma unroll
                for (int nd = 0; nd < 4; nd++) {
                    const uint4& B = V[nd >> 1][kf];
                    mma_bf16(O[mt][nd], Ph[mt][kf],
                             (nd & 1) ? B.y : B.x, (nd & 1) ? B.w : B.z);
                }
#pragma unroll
        for (int kf = 0; kf < 4; kf++)
#pragma unroll
            for (int mt = 0; mt < 2; mt++)
#pragma unroll
                for (int nd = 0; nd < 4; nd++) {
                    const uint4& B = V[nd >> 1][kf];
                    mma_bf16(O[mt][nd], Pl[mt][kf],
                             (nd & 1) ? B.y : B.x, (nd & 1) ? B.w : B.z);
                }
#pragma unroll
        for (int nf = 0; nf < 2; nf++)
#pragma unroll
            for (int kf = 0; kf < 4; kf++)
                V[nf][kf] = vl[(nf * 4 + kf) * 32 + lane];
#pragma unroll
        for (int kf = 0; kf < 4; kf++)
#pragma unroll
            for (int mt = 0; mt < 2; mt++)
#pragma unroll
                for (int nd = 0; nd < 4; nd++) {
                    const uint4& B = V[nd >> 1][kf];
                    mma_bf16(O[mt][nd], Ph[mt][kf],
                             (nd & 1) ? B.y : B.x, (nd & 1) ? B.w : B.z);
                }
    }

    // Epilogue: O -> attn-out A-frags (t = bw*64 + p, channel = head*32 + d)
#pragma unroll
    for (int mt = 0; mt < 2; mt++) {
        const int tf = bw * 4 + warp * 2 + mt;
#pragma unroll
        for (int nd = 0; nd < 4; nd++) {
            const int ch = head * 32 + nd * 8 + 2 * (lane & 3);
            const int chf = ch >> 4;
            uint32_t h0, l0, h1, l1;
            split2(O[mt][nd][0], O[mt][nd][1], h0, l0);
            split2(O[mt][nd][2], O[mt][nd][3], h1, l1);
            const size_t off = ((size_t)tf * 16 + chf) * 128 + lane * 4 + 2 * (nd & 1);
            ((uint32_t*)g_af_hi)[off]     = h0;
            ((uint32_t*)g_af_hi)[off + 1] = h1;
            ((uint32_t*)g_af_lo)[off]     = l0;
            ((uint32_t*)g_af_lo)[off + 1] = l1;
        }
    }
}

// ---------------------------------------------------------------------------
// Kernel 3: output projection, 128-thread CTA, warp tile 64x64; epilogue =
// scrambled reshape + roll.
// ---------------------------------------------------------------------------
__global__ __launch_bounds__(128)
void out_gemm(const float* __restrict__ bias, float* __restrict__ out) {
    const int tid = threadIdx.x;
    const int bn = blockIdx.x;   // 0..1
    const int bm = blockIdx.y;   // 0..2047
    const int lane = tid & 31;
    const int wid  = tid >> 5;
    const int warpM = wid & 1;
    const int warpN = wid >> 1;

    const int tfb = bm * 8 + warpM * 4;
    const int nfb = bn * 8 + warpN * 4;
    const uint4* pAh = (const uint4*)g_af_hi  + (size_t)tfb * 16 * 32 + lane;
    const uint4* pAl = (const uint4*)g_af_lo  + (size_t)tfb * 16 * 32 + lane;
    const uint4* pBh = (const uint4*)g_wof_hi + (size_t)nfb * 16 * 32 + lane;
    const uint4* pBl = (const uint4*)g_wof_lo + (size_t)nfb * 16 * 32 + lane;

    float acc[4][8][4];
#pragma unroll
    for (int a = 0; a < 4; a++)
#pragma unroll
        for (int b = 0; b < 8; b++)
#pragma unroll
            for (int cR = 0; cR < 4; cR++) acc[a][b][cR] = 0.f;

#pragma unroll
    for (int kf = 0; kf < 16; kf++) {
        uint4 Ah[4], Al[4], Bh[4], Bl[4];
#pragma unroll
        for (int mt = 0; mt < 4; mt++) {
            Ah[mt] = pAh[(mt * 16 + kf) * 32];
            Al[mt] = pAl[(mt * 16 + kf) * 32];
        }
#pragma unroll
        for (int nb = 0; nb < 4; nb++) {
            Bh[nb] = pBh[(nb * 16 + kf) * 32];
            Bl[nb] = pBl[(nb * 16 + kf) * 32];
        }
#pragma unroll
        for (int mt = 0; mt < 4; mt++)
#pragma unroll
            for (int nt = 0; nt < 8; nt++) {
                const uint4& B = Bh[nt >> 1];
                mma_bf16(acc[mt][nt], (const uint32_t*)&Ah[mt],
                         (nt & 1) ? B.y : B.x, (nt & 1) ? B.w : B.z);
            }
#pragma unroll
        for (int mt = 0; mt < 4; mt++)
#pragma unroll
            for (int nt = 0; nt < 8; nt++) {
                const uint4& B = Bh[nt >> 1];
                mma_bf16(acc[mt][nt], (const uint32_t*)&Al[mt],
                         (nt & 1) ? B.y : B.x, (nt & 1) ? B.w : B.z);
            }
#pragma unroll
        for (int mt = 0; mt < 4; mt++)
#pragma unroll
            for (int nt = 0; nt < 8; nt++) {
                const uint4& B = Bl[nt >> 1];
                mma_bf16(acc[mt][nt], (const uint32_t*)&Ah[mt],
                         (nt & 1) ? B.y : B.x, (nt & 1) ? B.w : B.z);
            }
    }

#pragma unroll
    for (int mt = 0; mt < 4; mt++) {
#pragma unroll
        for (int rr = 0; rr < 2; rr++) {
            const int gt   = bm * 128 + warpM * 64 + mt * 16 + (lane >> 2) + rr * 8;
            const int gbi  = gt >> 16;
            const int grem = gt & 65535;
            const int gwin = grem >> 6;
            const int gp   = grem & 63;
            const int L  = gwin * 4 + gbi;    // reference's scrambled flatten
            const int a  = L >> 10;
            const int r  = (L >> 5) & 31;
            const int s  = L & 31;
            const int hh  = ((r << 3) + (gp >> 3) + 4) & 255;
            const int wwp = ((s << 3) + (gp & 7) + 4) & 255;
            float* orow = out + ((((size_t)a << 8) + hh) * 256 + wwp) * 256;
#pragma unroll
            for (int nt = 0; nt < 8; nt++) {
                const int n = bn * 128 + warpN * 64 + nt * 8 + 2 * (lane & 3);
                *(float2*)&orow[n] =
                    make_float2(acc[mt][nt][rr * 2 + 0] + __ldg(bias + n),
                                acc[mt][nt][rr * 2 + 1] + __ldg(bias + n + 1));
            }
        }
    }
}

// ---------------------------------------------------------------------------
extern "C" void kernel_launch(void* const* d_in, const int* in_sizes, int n_in,
                              void* d_out, int out_size) {
    const float* x      = (const float*)d_in[0];
    const float* w_qkv  = (const float*)d_in[1];
    const float* b_qkv  = (const float*)d_in[2];
    const float* rel    = (const float*)d_in[3];
    const float* w_out  = (const float*)d_in[4];
    const float* b_out  = (const float*)d_in[5];
    float* out = (float*)d_out;

    __nv_bfloat16 *wq_hi, *wq_lo, *wo_hi, *wo_lo;
    cudaGetSymbolAddress((void**)&wq_hi, g_wqf_hi);
    cudaGetSymbolAddress((void**)&wq_lo, g_wqf_lo);
    cudaGetSymbolAddress((void**)&wo_hi, g_wof_hi);
    cudaGetSymbolAddress((void**)&wo_lo, g_wof_lo);

    cvt_x<<<32768, 256>>>(x);
    cvt_w<<<96, 256>>>(w_qkv, wq_hi, wq_lo);
    cvt_w<<<32, 256>>>(w_out, wo_hi, wo_lo);
    qkv_gemm<<<dim3(6, 2048), 128>>>(b_qkv);
    attn_kernel<<<32768, 64>>>(rel);
    out_gemm<<<dim3(2, 2048), 128>>>(b_out, out);
}

// round 10
// speedup vs baseline: 1.4768x; 1.2774x over previous
#include <cuda_runtime.h>
#include <cuda_bf16.h>
#include <cstdint>

// ---------------------------------------------------------------------------
// WMSA, b=4, H=W=256, c=256, WS=8, HEAD_DIM=32.
// R10: GEMMs use a 3-stage cp.async smem pipeline over the fragment-image
// layout (smem = byte-copy of frags; LDS.128 conflict-free). 128-thr CTAs,
// warp tile 64x32, CTA tile 128x64, 12 warps/SM. Attention/cvt = R7.
// ---------------------------------------------------------------------------

#define QKV_SCALE 0.1767766952966369f   // 32^-0.5

// Fragment arrays (bf16). frag = 256 bf16 = 128 u32 = 32 uint4 = 512 B.
__device__ __align__(16) __nv_bfloat16 g_xf_hi[67108864], g_xf_lo[67108864]; // x A-frags [tf][kf=16]
__device__ __align__(16) __nv_bfloat16 g_wqf_hi[196608],  g_wqf_lo[196608];  // w_qkv B-frags [nf=48][kf=16]
__device__ __align__(16) __nv_bfloat16 g_wof_hi[65536],   g_wof_lo[65536];   // w_out B-frags [nf=16][kf=16]
__device__ __align__(16) __nv_bfloat16 g_qf_hi[67108864], g_qf_lo[67108864]; // per blk A-frags
__device__ __align__(16) __nv_bfloat16 g_kf_hi[67108864], g_kf_lo[67108864]; // per blk B-frags
__device__ __align__(16) __nv_bfloat16 g_vf_hi[67108864], g_vf_lo[67108864]; // per blk VT B-frags
__device__ __align__(16) __nv_bfloat16 g_af_hi[67108864], g_af_lo[67108864]; // attn-out A-frags

// ---------------- helpers ----------------
__device__ __forceinline__ uint32_t smem_u32(const void* p) {
    uint32_t a;
    asm("{ .reg .u64 t; cvta.to.shared.u64 t, %1; cvt.u32.u64 %0, t; }"
        : "=r"(a) : "l"(p));
    return a;
}
__device__ __forceinline__ void mma_bf16(float* c, const uint32_t* a,
                                         uint32_t b0, uint32_t b1) {
    asm volatile(
        "mma.sync.aligned.m16n8k16.row.col.f32.bf16.bf16.f32 "
        "{%0,%1,%2,%3}, {%4,%5,%6,%7}, {%8,%9}, {%0,%1,%2,%3};"
        : "+f"(c[0]), "+f"(c[1]), "+f"(c[2]), "+f"(c[3])
        : "r"(a[0]), "r"(a[1]), "r"(a[2]), "r"(a[3]), "r"(b0), "r"(b1));
}
__device__ __forceinline__ void split2(float a, float b, uint32_t& h, uint32_t& l) {
    __nv_bfloat16 ha = __float2bfloat16(a), hb = __float2bfloat16(b);
    h = (uint32_t)__bfloat16_as_ushort(ha) | ((uint32_t)__bfloat16_as_ushort(hb) << 16);
    __nv_bfloat16 la = __float2bfloat16(a - __bfloat162float(ha));
    __nv_bfloat16 lb = __float2bfloat16(b - __bfloat162float(hb));
    l = (uint32_t)__bfloat16_as_ushort(la) | ((uint32_t)__bfloat16_as_ushort(lb) << 16);
}
__device__ __forceinline__ void cp16(uint32_t dst, const void* src) {
    asm volatile("cp.async.cg.shared.global [%0], [%1], 16;" :: "r"(dst), "l"(src));
}

// ---------------------------------------------------------------------------
// cvt_x: gathered (roll+window) tokens -> A-frags.
// ---------------------------------------------------------------------------
__global__ __launch_bounds__(256) void cvt_x(const float* __restrict__ x) {
    const int gid  = blockIdx.x * 256 + threadIdx.x;
    const int lane = gid & 31;
    const int f    = gid >> 5;          // tf*16 + kf
    const int kf   = f & 15, tf = f >> 4;
    const int r    = lane >> 2;
    const int c0   = kf * 16 + 2 * (lane & 3);
    int t = tf * 16 + r;
    const float* row0; const float* row1;
    {
        int bi = t >> 16, rem = t & 65535, win = rem >> 6, p = rem & 63;
        int hh = (((win >> 5) << 3) + (p >> 3) + 4) & 255;
        int ww = (((win & 31) << 3) + (p & 7) + 4) & 255;
        row0 = x + ((((size_t)bi << 8) + hh) * 256 + ww) * 256;
        t += 8;
        bi = t >> 16; rem = t & 65535; win = rem >> 6; p = rem & 63;
        hh = (((win >> 5) << 3) + (p >> 3) + 4) & 255;
        ww = (((win & 31) << 3) + (p & 7) + 4) & 255;
        row1 = x + ((((size_t)bi << 8) + hh) * 256 + ww) * 256;
    }
    float2 v00 = *(const float2*)(row0 + c0);
    float2 v10 = *(const float2*)(row1 + c0);
    float2 v01 = *(const float2*)(row0 + c0 + 8);
    float2 v11 = *(const float2*)(row1 + c0 + 8);
    uint4 h, l;
    split2(v00.x, v00.y, h.x, l.x);
    split2(v10.x, v10.y, h.y, l.y);
    split2(v01.x, v01.y, h.z, l.z);
    split2(v11.x, v11.y, h.w, l.w);
    ((uint4*)g_xf_hi)[(size_t)f * 32 + lane] = h;
    ((uint4*)g_xf_lo)[(size_t)f * 32 + lane] = l;
}

__global__ __launch_bounds__(256) void cvt_w(const float* __restrict__ w,
                                             __nv_bfloat16* __restrict__ hi,
                                             __nv_bfloat16* __restrict__ lo) {
    const int gid  = blockIdx.x * 256 + threadIdx.x;
    const int lane = gid & 31;
    const int f    = gid >> 5;          // nf*16 + kf
    const int kf   = f & 15, nf = f >> 4;
    const int r    = lane >> 2;
    const int c0   = kf * 16 + 2 * (lane & 3);
    const float* row0 = w + (size_t)(nf * 16 + r) * 256;
    const float* row1 = row0 + 8 * 256;
    float2 v00 = *(const float2*)(row0 + c0);
    float2 v10 = *(const float2*)(row1 + c0);
    float2 v01 = *(const float2*)(row0 + c0 + 8);
    float2 v11 = *(const float2*)(row1 + c0 + 8);
    uint4 h, l;
    split2(v00.x, v00.y, h.x, l.x);
    split2(v10.x, v10.y, h.y, l.y);
    split2(v01.x, v01.y, h.z, l.z);
    split2(v11.x, v11.y, h.w, l.w);
    ((uint4*)hi)[(size_t)f * 32 + lane] = h;
    ((uint4*)lo)[(size_t)f * 32 + lane] = l;
}

// ---------------------------------------------------------------------------
// Pipelined GEMM mainloop shared by kernels 1 and 3.
// CTA 128 thr, 2x2 warps of 64x32. Stage = 24 frags x 512 B = 12 KB:
//   slots 0-7 A-hi (tf), 8-15 A-lo, 16-19 B-hi (nf), 20-23 B-lo.
// ---------------------------------------------------------------------------
#define STAGE_U4 768   // 12 KB in uint4

struct GemmPtrs { const char *ah, *al, *bh, *bl; };

__device__ __forceinline__ void issue_stage(const GemmPtrs& g, int tfb, int nfb,
                                            int kf2, uint32_t smem_base, int tid) {
    const int stage = kf2 % 3;
    const int chunk = tid & 31;
    const int g0    = tid >> 5;          // 0..3
    const uint32_t dbase = smem_base + stage * 12288 + chunk * 16;
#pragma unroll
    for (int r = 0; r < 6; r++) {
        const int slot = g0 + 4 * r;
        const char* src;
        if (slot < 8)
            src = g.ah + ((size_t)((tfb + slot) * 16 + kf2)) * 512 + chunk * 16;
        else if (slot < 16)
            src = g.al + ((size_t)((tfb + slot - 8) * 16 + kf2)) * 512 + chunk * 16;
        else if (slot < 20)
            src = g.bh + ((size_t)((nfb + slot - 16) * 16 + kf2)) * 512 + chunk * 16;
        else
            src = g.bl + ((size_t)((nfb + slot - 20) * 16 + kf2)) * 512 + chunk * 16;
        cp16(dbase + slot * 512, src);
    }
    asm volatile("cp.async.commit_group;" ::: "memory");
}

// Runs the full 16-kf pipelined mainloop into acc[4][4][4].
__device__ __forceinline__ void gemm_mainloop(const GemmPtrs& g, int tfb, int nfb,
                                              uint4* smem, int tid,
                                              int warpM, int warpN, int lane,
                                              float acc[4][4][4]) {
    const uint32_t smem_base = smem_u32(smem);
    issue_stage(g, tfb, nfb, 0, smem_base, tid);
    issue_stage(g, tfb, nfb, 1, smem_base, tid);

#pragma unroll
    for (int kf = 0; kf < 16; kf++) {
        if (kf < 14)
            asm volatile("cp.async.wait_group 1;" ::: "memory");
        else
            asm volatile("cp.async.wait_group 0;" ::: "memory");
        __syncthreads();
        if (kf < 14) issue_stage(g, tfb, nfb, kf + 2, smem_base, tid);

        const int sb = (kf % 3) * STAGE_U4;
        uint4 Ah[4], Bh[2];
#pragma unroll
        for (int mt = 0; mt < 4; mt++)
            Ah[mt] = smem[sb + (warpM * 4 + mt) * 32 + lane];
#pragma unroll
        for (int nb = 0; nb < 2; nb++)
            Bh[nb] = smem[sb + 512 + (warpN * 2 + nb) * 32 + lane];
#pragma unroll
        for (int mt = 0; mt < 4; mt++)
#pragma unroll
            for (int nt = 0; nt < 4; nt++) {
                const uint4& B = Bh[nt >> 1];
                mma_bf16(acc[mt][nt], (const uint32_t*)&Ah[mt],
                         (nt & 1) ? B.y : B.x, (nt & 1) ? B.w : B.z);
            }
        uint4 Al[4];
#pragma unroll
        for (int mt = 0; mt < 4; mt++)
            Al[mt] = smem[sb + 256 + (warpM * 4 + mt) * 32 + lane];
#pragma unroll
        for (int mt = 0; mt < 4; mt++)
#pragma unroll
            for (int nt = 0; nt < 4; nt++) {
                const uint4& B = Bh[nt >> 1];
                mma_bf16(acc[mt][nt], (const uint32_t*)&Al[mt],
                         (nt & 1) ? B.y : B.x, (nt & 1) ? B.w : B.z);
            }
        uint4 Bl[2];
#pragma unroll
        for (int nb = 0; nb < 2; nb++)
            Bl[nb] = smem[sb + 640 + (warpN * 2 + nb) * 32 + lane];
#pragma unroll
        for (int mt = 0; mt < 4; mt++)
#pragma unroll
            for (int nt = 0; nt < 4; nt++) {
                const uint4& B = Bl[nt >> 1];
                mma_bf16(acc[mt][nt], (const uint32_t*)&Ah[mt],
                         (nt & 1) ? B.y : B.x, (nt & 1) ? B.w : B.z);
            }
    }
}

// ---------------------------------------------------------------------------
// Kernel 1: QKV GEMM. grid (12, 2048): bn = 64-col slab of N=768.
// ---------------------------------------------------------------------------
__global__ __launch_bounds__(128)
void qkv_gemm(const float* __restrict__ bias) {
    __shared__ __align__(16) uint4 smem[2304];   // 36 KB, 3 stages
    const int tid = threadIdx.x;
    const int bn = blockIdx.x;   // 0..11
    const int bm = blockIdx.y;   // 0..2047
    const int lane = tid & 31;
    const int wid  = tid >> 5;
    const int warpM = wid & 1;
    const int warpN = wid >> 1;

    float acc[4][4][4];
#pragma unroll
    for (int a = 0; a < 4; a++)
#pragma unroll
        for (int b = 0; b < 4; b++)
#pragma unroll
            for (int cR = 0; cR < 4; cR++) acc[a][b][cR] = 0.f;

    GemmPtrs g = { (const char*)g_xf_hi, (const char*)g_xf_lo,
                   (const char*)g_wqf_hi, (const char*)g_wqf_lo };
    gemm_mainloop(g, bm * 8, bn * 4, smem, tid, warpM, warpN, lane, acc);

    // Epilogue: q/k/v frag-ready scatter (R7-verified math; n-base adapted).
    const bool isq = (bn < 4);
    const bool isv = (bn >= 8);
    const int bwq = bm * 2 + warpM;
#pragma unroll
    for (int nt = 0; nt < 4; nt++) {
        const int n = bn * 64 + warpN * 32 + nt * 8 + 2 * (lane & 3);
        const float b0 = __ldg(bias + n), b1 = __ldg(bias + n + 1);
        const int head = (n >> 5) & 7;
        const int d0 = n & 31;
        const size_t blkbase = ((size_t)bwq * 8 + head) * 1024;  // u32 units
#pragma unroll
        for (int mt = 0; mt < 4; mt++) {
#pragma unroll
            for (int rr = 0; rr < 2; rr++) {
                float v0 = acc[mt][nt][rr * 2 + 0] + b0;
                float v1 = acc[mt][nt][rr * 2 + 1] + b1;
                if (isq) { v0 *= QKV_SCALE; v1 *= QKV_SCALE; }
                const int gp = mt * 16 + (lane >> 2) + rr * 8;
                if (!isv) {
                    uint32_t h, l;
                    split2(v0, v1, h, l);
                    const int frag = (gp >> 4) * 2 + (d0 >> 4);
                    const int reg = rr + 2 * (nt & 1);
                    const size_t off = blkbase + frag * 128 + lane * 4 + reg;
                    if (isq) {
                        ((uint32_t*)g_qf_hi)[off] = h;
                        ((uint32_t*)g_qf_lo)[off] = l;
                    } else {
                        ((uint32_t*)g_kf_hi)[off] = h;
                        ((uint32_t*)g_kf_lo)[off] = l;
                    }
                } else {
                    const float p0 = __shfl_xor_sync(0xffffffffu, v0, 4);
                    const float p1 = __shfl_xor_sync(0xffffffffu, v1, 4);
                    const bool odd = (lane >> 2) & 1;
                    const float e0 = odd ? p1 : v0;
                    const float e1 = odd ? v1 : p0;
                    const int dmy = d0 + (odd ? 1 : 0);
                    const int gpe = gp & ~1;
                    const int frag = (dmy >> 4) * 4 + (gpe >> 4);
                    const int lane2 = (dmy & 7) * 4 + ((gpe & 7) >> 1);
                    const int reg = (nt & 1) + 2 * rr;
                    uint32_t h, l;
                    split2(e0, e1, h, l);
                    const size_t off = blkbase + frag * 128 + lane2 * 4 + reg;
                    ((uint32_t*)g_vf_hi)[off] = h;
                    ((uint32_t*)g_vf_lo)[off] = l;
                }
            }
        }
    }
}

// ---------------------------------------------------------------------------
// Kernel 2: attention via mma (R7, verified). One 64-thr block per (b,win,head).
// ---------------------------------------------------------------------------
__global__ __launch_bounds__(64) void attn_kernel(const float* __restrict__ rel_pos) {
    const int blk  = blockIdx.x;
    const int head = blk & 7;
    const int bw   = blk >> 3;
    const int win  = bw & 1023;
    const bool lastH = ((win >> 5) == 31);
    const bool lastW = ((win & 31) == 31);
    const int lane = threadIdx.x & 31;
    const int warp = threadIdx.x >> 5;

    __shared__ float rel_s[240];
    for (int i = threadIdx.x; i < 225; i += 64) rel_s[i] = rel_pos[head * 225 + i];
    __syncthreads();

    const uint4* qh = (const uint4*)g_qf_hi + (size_t)blk * 256;
    const uint4* ql = (const uint4*)g_qf_lo + (size_t)blk * 256;
    const uint4* kh = (const uint4*)g_kf_hi + (size_t)blk * 256;
    const uint4* kl = (const uint4*)g_kf_lo + (size_t)blk * 256;
    const uint4* vh = (const uint4*)g_vf_hi + (size_t)blk * 256;
    const uint4* vl = (const uint4*)g_vf_lo + (size_t)blk * 256;

    float S[2][8][4];
#pragma unroll
    for (int a = 0; a < 2; a++)
#pragma unroll
        for (int b = 0; b < 8; b++)
#pragma unroll
            for (int cR = 0; cR < 4; cR++) S[a][b][cR] = 0.f;

    {
        uint4 Q[2][2], K[4][2];
#pragma unroll
        for (int mt = 0; mt < 2; mt++)
#pragma unroll
            for (int kf = 0; kf < 2; kf++)
                Q[mt][kf] = qh[((2 * warp + mt) * 2 + kf) * 32 + lane];
#pragma unroll
        for (int nf = 0; nf < 4; nf++)
#pragma unroll
            for (int kf = 0; kf < 2; kf++)
                K[nf][kf] = kh[(nf * 2 + kf) * 32 + lane];
#pragma unroll
        for (int kf = 0; kf < 2; kf++)
#pragma unroll
            for (int mt = 0; mt < 2; mt++)
#pragma unroll
                for (int nt = 0; nt < 8; nt++) {
                    const uint4& B = K[nt >> 1][kf];
                    mma_bf16(S[mt][nt], (const uint32_t*)&Q[mt][kf],
                             (nt & 1) ? B.y : B.x, (nt & 1) ? B.w : B.z);
                }
        uint4 Q2[2][2];
#pragma unroll
        for (int mt = 0; mt < 2; mt++)
#pragma unroll
            for (int kf = 0; kf < 2; kf++)
                Q2[mt][kf] = ql[((2 * warp + mt) * 2 + kf) * 32 + lane];
#pragma unroll
        for (int kf = 0; kf < 2; kf++)
#pragma unroll
            for (int mt = 0; mt < 2; mt++)
#pragma unroll
                for (int nt = 0; nt < 8; nt++) {
                    const uint4& B = K[nt >> 1][kf];
                    mma_bf16(S[mt][nt], (const uint32_t*)&Q2[mt][kf],
                             (nt & 1) ? B.y : B.x, (nt & 1) ? B.w : B.z);
                }
#pragma unroll
        for (int nf = 0; nf < 4; nf++)
#pragma unroll
            for (int kf = 0; kf < 2; kf++)
                K[nf][kf] = kl[(nf * 2 + kf) * 32 + lane];
#pragma unroll
        for (int kf = 0; kf < 2; kf++)
#pragma unroll
            for (int mt = 0; mt < 2; mt++)
#pragma unroll
                for (int nt = 0; nt < 8; nt++) {
                    const uint4& B = K[nt >> 1][kf];
                    mma_bf16(S[mt][nt], (const uint32_t*)&Q[mt][kf],
                             (nt & 1) ? B.y : B.x, (nt & 1) ? B.w : B.z);
                }
    }

#pragma unroll
    for (int mt = 0; mt < 2; mt++) {
        const int p_lo = warp * 32 + mt * 16 + (lane >> 2);
        const int p_hi = p_lo + 8;
        const int pi0 = p_lo >> 3, pj0 = p_lo & 7;
        const int pi1 = p_hi >> 3, pj1 = p_hi & 7;
#pragma unroll
        for (int nt = 0; nt < 8; nt++) {
            const int j0 = nt * 8 + 2 * (lane & 3);
#pragma unroll
            for (int jj = 0; jj < 2; jj++) {
                const int j = j0 + jj;
                const int qi = j >> 3, qj = j & 7;
                float r0 = rel_s[(pi0 - qi + 7) * 15 + (pj0 - qj + 7)];
                float r1 = rel_s[(pi1 - qi + 7) * 15 + (pj1 - qj + 7)];
                float s0 = S[mt][nt][jj] + r0;
                float s1 = S[mt][nt][2 + jj] + r1;
                if ((lastH && ((pi0 < 4) != (qi < 4))) || (lastW && ((pj0 < 4) != (qj < 4))))
                    s0 = -1e30f;
                if ((lastH && ((pi1 < 4) != (qi < 4))) || (lastW && ((pj1 < 4) != (qj < 4))))
                    s1 = -1e30f;
                S[mt][nt][jj] = s0;
                S[mt][nt][2 + jj] = s1;
            }
        }
    }

    float O[2][4][4];
#pragma unroll
    for (int a = 0; a < 2; a++)
#pragma unroll
        for (int b = 0; b < 4; b++)
#pragma unroll
            for (int cR = 0; cR < 4; cR++) O[a][b][cR] = 0.f;

    uint32_t Ph[2][4][4], Pl[2][4][4];
#pragma unroll
    for (int mt = 0; mt < 2; mt++) {
        float m0 = -3.0e38f, m1 = -3.0e38f;
#pragma unroll
        for (int nt = 0; nt < 8; nt++) {
            m0 = fmaxf(m0, fmaxf(S[mt][nt][0], S[mt][nt][1]));
            m1 = fmaxf(m1, fmaxf(S[mt][nt][2], S[mt][nt][3]));
        }
        m0 = fmaxf(m0, __shfl_xor_sync(0xffffffffu, m0, 1));
        m0 = fmaxf(m0, __shfl_xor_sync(0xffffffffu, m0, 2));
        m1 = fmaxf(m1, __shfl_xor_sync(0xffffffffu, m1, 1));
        m1 = fmaxf(m1, __shfl_xor_sync(0xffffffffu, m1, 2));
        float s0 = 0.f, s1 = 0.f;
#pragma unroll
        for (int nt = 0; nt < 8; nt++) {
            S[mt][nt][0] = __expf(S[mt][nt][0] - m0);
            S[mt][nt][1] = __expf(S[mt][nt][1] - m0);
            S[mt][nt][2] = __expf(S[mt][nt][2] - m1);
            S[mt][nt][3] = __expf(S[mt][nt][3] - m1);
            s0 += S[mt][nt][0] + S[mt][nt][1];
            s1 += S[mt][nt][2] + S[mt][nt][3];
        }
        s0 += __shfl_xor_sync(0xffffffffu, s0, 1);
        s0 += __shfl_xor_sync(0xffffffffu, s0, 2);
        s1 += __shfl_xor_sync(0xffffffffu, s1, 1);
        s1 += __shfl_xor_sync(0xffffffffu, s1, 2);
        const float i0 = 1.f / s0, i1 = 1.f / s1;
#pragma unroll
        for (int kf = 0; kf < 4; kf++) {
            split2(S[mt][2 * kf][0] * i0, S[mt][2 * kf][1] * i0, Ph[mt][kf][0], Pl[mt][kf][0]);
            split2(S[mt][2 * kf][2] * i1, S[mt][2 * kf][3] * i1, Ph[mt][kf][1], Pl[mt][kf][1]);
            split2(S[mt][2 * kf + 1][0] * i0, S[mt][2 * kf + 1][1] * i0, Ph[mt][kf][2], Pl[mt][kf][2]);
            split2(S[mt][2 * kf + 1][2] * i1, S[mt][2 * kf + 1][3] * i1, Ph[mt][kf][3], Pl[mt][kf][3]);
        }
    }

    {
        uint4 V[2][4];
#pragma unroll
        for (int nf = 0; nf < 2; nf++)
#pragma unroll
            for (int kf = 0; kf < 4; kf++)
                V[nf][kf] = vh[(nf * 4 + kf) * 32 + lane];
#pragma unroll
        for (int kf = 0; kf < 4; kf++)
#pragma unroll
            for (int mt = 0; mt < 2; mt++)
#pragma unroll
                for (int nd = 0; nd < 4; nd++) {
                    const uint4& B = V[nd >> 1][kf];
                    mma_bf16(O[mt][nd], Ph[mt][kf],
                             (nd & 1) ? B.y : B.x, (nd & 1) ? B.w : B.z);
                }
#pragma unroll
        for (int kf = 0; kf < 4; kf++)
#pragma unroll
            for (int mt = 0; mt < 2; mt++)
#pragma unroll
                for (int nd = 0; nd < 4; nd++) {
                    const uint4& B = V[nd >> 1][kf];
                    mma_bf16(O[mt][nd], Pl[mt][kf],
                             (nd & 1) ? B.y : B.x, (nd & 1) ? B.w : B.z);
                }
#pragma unroll
        for (int nf = 0; nf < 2; nf++)
#pragma unroll
            for (int kf = 0; kf < 4; kf++)
                V[nf][kf] = vl[(nf * 4 + kf) * 32 + lane];
#pragma unroll
        for (int kf = 0; kf < 4; kf++)
#pragma unroll
            for (int mt = 0; mt < 2; mt++)
#pragma unroll
                for (int nd = 0; nd < 4; nd++) {
                    const uint4& B = V[nd >> 1][kf];
                    mma_bf16(O[mt][nd], Ph[mt][kf],
                             (nd & 1) ? B.y : B.x, (nd & 1) ? B.w : B.z);
                }
    }

#pragma unroll
    for (int mt = 0; mt < 2; mt++) {
        const int tf = bw * 4 + warp * 2 + mt;
#pragma unroll
        for (int nd = 0; nd < 4; nd++) {
            const int ch = head * 32 + nd * 8 + 2 * (lane & 3);
            const int chf = ch >> 4;
            uint32_t h0, l0, h1, l1;
            split2(O[mt][nd][0], O[mt][nd][1], h0, l0);
            split2(O[mt][nd][2], O[mt][nd][3], h1, l1);
            const size_t off = ((size_t)tf * 16 + chf) * 128 + lane * 4 + 2 * (nd & 1);
            ((uint32_t*)g_af_hi)[off]     = h0;
            ((uint32_t*)g_af_hi)[off + 1] = h1;
            ((uint32_t*)g_af_lo)[off]     = l0;
            ((uint32_t*)g_af_lo)[off + 1] = l1;
        }
    }
}

// ---------------------------------------------------------------------------
// Kernel 3: output projection, pipelined; grid (4, 2048).
// ---------------------------------------------------------------------------
__global__ __launch_bounds__(128)
void out_gemm(const float* __restrict__ bias, float* __restrict__ out) {
    __shared__ __align__(16) uint4 smem[2304];
    const int tid = threadIdx.x;
    const int bn = blockIdx.x;   // 0..3
    const int bm = blockIdx.y;   // 0..2047
    const int lane = tid & 31;
    const int wid  = tid >> 5;
    const int warpM = wid & 1;
    const int warpN = wid >> 1;

    float acc[4][4][4];
#pragma unroll
    for (int a = 0; a < 4; a++)
#pragma unroll
        for (int b = 0; b < 4; b++)
#pragma unroll
            for (int cR = 0; cR < 4; cR++) acc[a][b][cR] = 0.f;

    GemmPtrs g = { (const char*)g_af_hi, (const char*)g_af_lo,
                   (const char*)g_wof_hi, (const char*)g_wof_lo };
    gemm_mainloop(g, bm * 8, bn * 4, smem, tid, warpM, warpN, lane, acc);

#pragma unroll
    for (int mt = 0; mt < 4; mt++) {
#pragma unroll
        for (int rr = 0; rr < 2; rr++) {
            const int gt   = bm * 128 + warpM * 64 + mt * 16 + (lane >> 2) + rr * 8;
            const int gbi  = gt >> 16;
            const int grem = gt & 65535;
            const int gwin = grem >> 6;
            const int gp   = grem & 63;
            const int L  = gwin * 4 + gbi;    // reference's scrambled flatten
            const int a  = L >> 10;
            const int r  = (L >> 5) & 31;
            const int s  = L & 31;
            const int hh  = ((r << 3) + (gp >> 3) + 4) & 255;
            const int wwp = ((s << 3) + (gp & 7) + 4) & 255;
            float* orow = out + ((((size_t)a << 8) + hh) * 256 + wwp) * 256;
#pragma unroll
            for (int nt = 0; nt < 4; nt++) {
                const int n = bn * 64 + warpN * 32 + nt * 8 + 2 * (lane & 3);
                *(float2*)&orow[n] =
                    make_float2(acc[mt][nt][rr * 2 + 0] + __ldg(bias + n),
                                acc[mt][nt][rr * 2 + 1] + __ldg(bias + n + 1));
            }
        }
    }
}

// ---------------------------------------------------------------------------
extern "C" void kernel_launch(void* const* d_in, const int* in_sizes, int n_in,
                              void* d_out, int out_size) {
    const float* x      = (const float*)d_in[0];
    const float* w_qkv  = (const float*)d_in[1];
    const float* b_qkv  = (const float*)d_in[2];
    const float* rel    = (const float*)d_in[3];
    const float* w_out  = (const float*)d_in[4];
    const float* b_out  = (const float*)d_in[5];
    float* out = (float*)d_out;

    __nv_bfloat16 *wq_hi, *wq_lo, *wo_hi, *wo_lo;
    cudaGetSymbolAddress((void**)&wq_hi, g_wqf_hi);
    cudaGetSymbolAddress((void**)&wq_lo, g_wqf_lo);
    cudaGetSymbolAddress((void**)&wo_hi, g_wof_hi);
    cudaGetSymbolAddress((void**)&wo_lo, g_wof_lo);

    cvt_x<<<32768, 256>>>(x);
    cvt_w<<<96, 256>>>(w_qkv, wq_hi, wq_lo);
    cvt_w<<<32, 256>>>(w_out, wo_hi, wo_lo);
    qkv_gemm<<<dim3(12, 2048), 128>>>(b_qkv);
    attn_kernel<<<32768, 64>>>(rel);
    out_gemm<<<dim3(4, 2048), 128>>>(b_out, out);
}